// round 16
// baseline (speedup 1.0000x reference)
#include <cuda_runtime.h>
#include <cstdint>
#include <cstddef>

// Problem constants
#define BB 32
#define TT 256
#define DD 512
#define HH 1024
#define GN 4096          // 4*H gate columns
#define MM (BB*TT)       // 8192 rows

#define NCTA 256         // persistent CTAs (2/SM on loaded SMs)
#define UPC 4            // hidden units per CTA (x4 gates = 16 cols)
#define PTH 256          // threads per CTA

// ---------------- scratch (static device allocations; no cudaMalloc) -------
__device__ float g_zx[(size_t)MM * GN];      // input-projection Z (128 MB)
__device__ float g_h1[(size_t)MM * HH];      // layer-1 hidden history (32 MB)
__device__ float g_hT[2][HH * BB];           // transposed h double buffer [unit][batch]
__device__ unsigned g_bar_count;
__device__ unsigned g_bar_phase;

// ---------------- f32x2 packed FMA (Blackwell FFMA2) -----------------------
__device__ __forceinline__ float2 ffma2(float2 a, float2 b, float2 c) {
    unsigned long long au = *reinterpret_cast<unsigned long long*>(&a);
    unsigned long long bu = *reinterpret_cast<unsigned long long*>(&b);
    unsigned long long cu = *reinterpret_cast<unsigned long long*>(&c);
    unsigned long long du;
    asm("fma.rn.f32x2 %0, %1, %2, %3;" : "=l"(du) : "l"(au), "l"(bu), "l"(cu));
    return *reinterpret_cast<float2*>(&du);
}

// ---------------- fast activations (MUFU-based, inf-safe) -------------------
__device__ __forceinline__ float sig_fast(float x) {
    return __fdividef(1.f, 1.f + __expf(-x));
}
__device__ __forceinline__ float tanh_fast(float x) {
    return __fdividef(2.f, 1.f + __expf(-2.f * x)) - 1.f;
}

// ---------------- cp.async helpers ------------------------------------------
__device__ __forceinline__ void cp_async16(uint32_t dst_smem, const void* src) {
    asm volatile("cp.async.cg.shared.global [%0], [%1], 16;" :: "r"(dst_smem), "l"(src));
}
__device__ __forceinline__ void cp_commit() {
    asm volatile("cp.async.commit_group;" ::: "memory");
}
template <int N>
__device__ __forceinline__ void cp_wait() {
    asm volatile("cp.async.wait_group %0;" :: "n"(N) : "memory");
}

// ---------------- big time-parallel GEMM: C[M,N] = A[M,K] * B[K,N] ---------
#define GM_BM 128
#define GM_BN 128
#define GM_BK 16

__global__ __launch_bounds__(256, 2) void sgemm_kernel(
    const float* __restrict__ A, const float* __restrict__ B,
    float* __restrict__ C, int M, int N, int K)
{
    __shared__ float As[GM_BK][GM_BM];
    __shared__ float Bs[GM_BK][GM_BN];

    const int tid = threadIdx.x;
    const int m0 = blockIdx.y * GM_BM;
    const int n0 = blockIdx.x * GM_BN;
    const int tx = tid & 15;
    const int ty = tid >> 4;

    float2 acc2[8][4];
#pragma unroll
    for (int i = 0; i < 8; i++)
#pragma unroll
        for (int j = 0; j < 4; j++) acc2[i][j] = make_float2(0.f, 0.f);

    for (int k0 = 0; k0 < K; k0 += GM_BK) {
#pragma unroll
        for (int l = 0; l < 2; ++l) {
            int i = tid + l * 256;
            int row = i >> 2;
            int kq = (i & 3) << 2;
            float4 v = *(const float4*)(A + (size_t)(m0 + row) * K + k0 + kq);
            As[kq + 0][row] = v.x;
            As[kq + 1][row] = v.y;
            As[kq + 2][row] = v.z;
            As[kq + 3][row] = v.w;
        }
#pragma unroll
        for (int l = 0; l < 2; ++l) {
            int i = tid + l * 256;
            int kr = i >> 5;
            int nq = (i & 31) << 2;
            *(float4*)(&Bs[kr][nq]) = *(const float4*)(B + (size_t)(k0 + kr) * N + n0 + nq);
        }
        __syncthreads();

#pragma unroll
        for (int k = 0; k < GM_BK; ++k) {
            float a[8];
            *(float4*)&a[0] = *(const float4*)&As[k][ty * 4];
            *(float4*)&a[4] = *(const float4*)&As[k][64 + ty * 4];
            float4 bv0 = *(const float4*)&Bs[k][tx * 4];
            float4 bv1 = *(const float4*)&Bs[k][64 + tx * 4];
            float2 b2[4];
            b2[0] = make_float2(bv0.x, bv0.y);
            b2[1] = make_float2(bv0.z, bv0.w);
            b2[2] = make_float2(bv1.x, bv1.y);
            b2[3] = make_float2(bv1.z, bv1.w);
#pragma unroll
            for (int i = 0; i < 8; i++) {
                float2 ad = make_float2(a[i], a[i]);
#pragma unroll
                for (int jp = 0; jp < 4; jp++)
                    acc2[i][jp] = ffma2(ad, b2[jp], acc2[i][jp]);
            }
        }
        __syncthreads();
    }

#pragma unroll
    for (int i = 0; i < 8; i++) {
        int row = m0 + ((i < 4) ? (ty * 4 + i) : (64 + ty * 4 + (i - 4)));
        float* cp = C + (size_t)row * N + n0;
        float4 v0 = make_float4(acc2[i][0].x, acc2[i][0].y, acc2[i][1].x, acc2[i][1].y);
        float4 v1 = make_float4(acc2[i][2].x, acc2[i][2].y, acc2[i][3].x, acc2[i][3].y);
        *(float4*)(cp + tx * 4) = v0;
        *(float4*)(cp + 64 + tx * 4) = v1;
    }
}

// ---------------- reset: barrier counters + h state ------------------------
__global__ void reset_kernel() {
    int i = blockIdx.x * blockDim.x + threadIdx.x;
    if (i == 0) { g_bar_count = 0; g_bar_phase = 0; }
    if (i < 2 * HH * BB) ((float*)g_hT)[i] = 0.f;
}

// ---------------- persistent LSTM layer kernel -----------------------------
// 256 CTAs x 256 threads, 2 CTAs/SM (independent sync domains -> cross-CTA
// stall hiding). CTA bx owns units [bx*4,bx*4+4) x 4 gates (16 cols), weight
// slice 64KB in smem. Thread (cq,bq,kq): cols {4cq..4cq+3} x batches
// {4bq..4bq+3}, K eighth kq. Per k: 1 LDS.128 w + 1 LDS.128 h (broadcast) ->
// 8 FFMA2. h streamed in 8 triple-buffered cp.async chunks (1 sync/chunk,
// rotated start); z staging overlaid on h buffer 2 (free during chunk 7).
// Central grid barrier (256 arrivals), tight spin, single poller per CTA.
// smem/CTA: w 64KB + h 3x16KB = 112KB  -> 224KB/SM (2 CTAs)
__global__ __launch_bounds__(PTH, 2) void lstm_persistent(
    const float* __restrict__ Wh,       // [HH][GN] recurrent weights
    const float* __restrict__ zx,       // [MM][GN], row = b*TT + t
    const float* __restrict__ bias,     // [GN]
    float* __restrict__ hist)           // [MM][HH] h history out
{
    extern __shared__ float smem[];
    float* w_s = smem;                           // [k*16 + cc], 16384 floats
    float* h_s = smem + 16384;                   // 3 x 4096 floats
    float* z_s = h_s + 2 * 4096;                 // overlaid on h buffer 2:
                                                 // 8 kq x 16 cols x 32 = 4096

    const int tid = threadIdx.x;
    const int bx = blockIdx.x;
    const int u0 = bx * UPC;
    const int start = bx & 7;            // rotated chunk start
    const int cq = tid & 3;              // col quad: cols {4cq..4cq+3} of 16
    const int bq = (tid >> 2) & 7;       // batch quad
    const int kq = tid >> 5;             // K eighth 0..7 (uniform per warp)
    const int gu = tid & 3;              // gate-phase unit   (tid < 128)
    const int gb = tid >> 2;             // gate-phase batch  (tid < 128)

    float* hT = (float*)g_hT;

    // ---- load weight slice into smem: w_s[k*16 + cc], cc = gate*4 + unit ----
#pragma unroll 8
    for (int l = 0; l < 64; ++l) {
        int i = tid + l * PTH;           // 0..16383
        int k = i >> 4;
        int cc = i & 15;
        int col = ((cc >> 2) << 10) + u0 + (cc & 3);
        w_s[i] = Wh[(size_t)k * GN + col];
    }

    float bi = 0.f, bj = 0.f, bf = 0.f, bo = 0.f;
    if (tid < 128) {
        bi = bias[0 * HH + u0 + gu];
        bj = bias[1 * HH + u0 + gu];
        bf = bias[2 * HH + u0 + gu];
        bo = bias[3 * HH + u0 + gu];
    }

    float creg = 0.f;
    __syncthreads();

    // per-thread chunk-load geometry: 4 float4s/thread/chunk (16KB chunk)
    const int ld_row = tid >> 3;          // base row 0..31 (stride 32)
    const int ld_c4 = (tid & 7) << 2;     // 0,4,..28

    for (int t = 0; t < TT; ++t) {
        const float* hread = hT + (t & 1) * (HH * BB);
        float* hwrite = hT + ((t + 1) & 1) * (HH * BB);

        // prefetch this step's zx for the gate phase (threads 0..127)
        float zxi = 0.f, zxj = 0.f, zxf = 0.f, zxo = 0.f;
        if (tid < 128) {
            const float* zxr = zx + (size_t)(gb * TT + t) * GN + u0 + gu;
            zxi = __ldg(zxr);
            zxj = __ldg(zxr + HH);
            zxf = __ldg(zxr + 2 * HH);
            zxo = __ldg(zxr + 3 * HH);
        }

        // ---- prologue: issue chunks start, start+1 into bufs 0, 1 ----
#pragma unroll
        for (int p = 0; p < 2; ++p) {
            uint32_t dst = (uint32_t)__cvta_generic_to_shared(h_s + p * 4096);
            const float* src = hread + ((start + p) & 7) * 128 * BB;
#pragma unroll
            for (int l = 0; l < 4; ++l) {
                int row = ld_row + l * 32;
                cp_async16(dst + (row * 32 + ld_c4) * 4, src + row * BB + ld_c4);
            }
            cp_commit();
        }

        float2 alo[4], ahi[4];
#pragma unroll
        for (int c = 0; c < 4; ++c) {
            alo[c] = make_float2(0.f, 0.f);
            ahi[c] = make_float2(0.f, 0.f);
        }

#pragma unroll 1
        for (int i = 0; i < 8; ++i) {
            int cs = (start + i) & 7;
            if (i < 7) cp_wait<1>(); else cp_wait<0>();
            __syncthreads();   // chunk i visible; buf (i+2)%3 free

            if (i < 6) {       // prefetch chunk i+2 into buf (i+2)%3
                uint32_t dst = (uint32_t)__cvta_generic_to_shared(
                    h_s + ((i + 2) % 3) * 4096);
                const float* src = hread + ((start + i + 2) & 7) * 128 * BB;
#pragma unroll
                for (int l = 0; l < 4; ++l) {
                    int row = ld_row + l * 32;
                    cp_async16(dst + (row * 32 + ld_c4) * 4, src + row * BB + ld_c4);
                }
                cp_commit();
            }

            const float* hb = h_s + (i % 3) * 4096 + (kq * 16) * 32 + bq * 4;
            const float* wb = w_s + (cs * 128 + kq * 16) * 16 + cq * 4;
#pragma unroll
            for (int kk = 0; kk < 16; ++kk) {
                float4 wv = *(const float4*)(wb + kk * 16);
                float4 hv = *(const float4*)(hb + kk * 32);
                float2 hlo = make_float2(hv.x, hv.y);
                float2 hhi = make_float2(hv.z, hv.w);
                alo[0] = ffma2(hlo, make_float2(wv.x, wv.x), alo[0]);
                ahi[0] = ffma2(hhi, make_float2(wv.x, wv.x), ahi[0]);
                alo[1] = ffma2(hlo, make_float2(wv.y, wv.y), alo[1]);
                ahi[1] = ffma2(hhi, make_float2(wv.y, wv.y), ahi[1]);
                alo[2] = ffma2(hlo, make_float2(wv.z, wv.z), alo[2]);
                ahi[2] = ffma2(hhi, make_float2(wv.z, wv.z), ahi[2]);
                alo[3] = ffma2(hlo, make_float2(wv.w, wv.w), alo[3]);
                ahi[3] = ffma2(hhi, make_float2(wv.w, wv.w), ahi[3]);
            }
        }
        // NOTE: chunk 7 lives in buf 1; bufs 0 and 2 are consumed. z_s (buf 2)
        // is safe to write now without an extra sync: all warps' last reads
        // target buf 1 only, and buf-2 reads ended before the i=7 sync.

        // stage K-eighth partials into z_s (buf 2 overlay), stride 32
        float* zh = z_s + kq * 512;          // 16 cols x 32
#pragma unroll
        for (int c = 0; c < 4; ++c) {
            *(float4*)(zh + (cq * 4 + c) * 32 + bq * 4) =
                make_float4(alo[c].x, alo[c].y, ahi[c].x, ahi[c].y);
        }
        __syncthreads();

        // ---- gate phase: threads 0..127 = (unit gu, batch gb) ----
        if (tid < 128) {
            float zi = zxi + bi, zj = zxj + bj, zf = zxf + bf, zo = zxo + bo;
#pragma unroll
            for (int q = 0; q < 8; ++q) {
                const float* zq = z_s + q * 512;
                zi += zq[(0 * 4 + gu) * 32 + gb];
                zj += zq[(1 * 4 + gu) * 32 + gb];
                zf += zq[(2 * 4 + gu) * 32 + gb];
                zo += zq[(3 * 4 + gu) * 32 + gb];
            }

            float ig = sig_fast(zi);
            float fg = sig_fast(zf + 1.0f);    // forget bias 1.0
            float jt = tanh_fast(zj);
            float cn = fg * creg + ig * jt;
            float og = sig_fast(zo);
            float hn = og * tanh_fast(cn);
            creg = cn;

            hwrite[(u0 + gu) * BB + gb] = hn;
            hist[(size_t)(gb * TT + t) * HH + u0 + gu] = hn;
        }

        // ---- central grid barrier (256 arrivals), tight spin ----
        if (t < TT - 1) {
            __syncthreads();   // CTA's h writes issued (also z_s guard)
            unsigned target = (unsigned)(t + 1);
            if (tid == 0) {
                unsigned prev;
                asm volatile("atom.add.release.gpu.global.u32 %0, [%1], 1;"
                             : "=r"(prev) : "l"(&g_bar_count) : "memory");
                if (prev == NCTA - 1) {
                    g_bar_count = 0;   // ordered by st.release below
                    asm volatile("st.release.gpu.global.u32 [%0], %1;"
                                 :: "l"(&g_bar_phase), "r"(target) : "memory");
                } else {
                    unsigned ph;
                    do {
                        asm volatile("ld.acquire.gpu.global.u32 %0, [%1];"
                                     : "=r"(ph) : "l"(&g_bar_phase) : "memory");
                    } while (ph < target);
                }
            }
            __syncthreads();
        } else {
            __syncthreads();
        }
    }
}

// ---------------- host orchestration ---------------------------------------
extern "C" void kernel_launch(void* const* d_in, const int* in_sizes, int n_in,
                              void* d_out, int out_size)
{
    const float *x = nullptr, *W1 = nullptr, *b1 = nullptr, *W2 = nullptr, *b2 = nullptr;
    for (int i = 0; i < n_in; i++) {
        int s = in_sizes[i];
        const float* p = (const float*)d_in[i];
        if (s == BB * TT * DD) x = p;
        else if (s == (DD + HH) * GN) W1 = p;
        else if (s == (HH + HH) * GN) W2 = p;
        else if (s == GN) { if (!b1) b1 = p; else b2 = p; }
    }
    float* out = (float*)d_out;

    float *zx, *h1;
    { void* p; cudaGetSymbolAddress(&p, g_zx); zx = (float*)p; }
    { void* p; cudaGetSymbolAddress(&p, g_h1); h1 = (float*)p; }

    const int SMEM_BYTES = (16384 + 3 * 4096) * 4;   // 112 KB per CTA
    cudaFuncSetAttribute(lstm_persistent,
                         cudaFuncAttributeMaxDynamicSharedMemorySize, SMEM_BYTES);

    dim3 gemm_grid(GN / GM_BN, MM / GM_BM);   // (32, 64)

    // ---- Layer 1 ----
    sgemm_kernel<<<gemm_grid, 256>>>(x, W1, zx, MM, GN, DD);
    reset_kernel<<<(2 * HH * BB + 255) / 256, 256>>>();
    // extra (idempotent) reset keeps lstm_persistent as ncu's captured launch
    reset_kernel<<<(2 * HH * BB + 255) / 256, 256>>>();
    lstm_persistent<<<NCTA, PTH, SMEM_BYTES>>>(W1 + (size_t)DD * GN, zx, b1, h1);

    // ---- Layer 2 ----
    sgemm_kernel<<<gemm_grid, 256>>>(h1, W2, zx, MM, GN, HH);
    reset_kernel<<<(2 * HH * BB + 255) / 256, 256>>>();
    lstm_persistent<<<NCTA, PTH, SMEM_BYTES>>>(W2 + (size_t)HH * GN, zx, b2, out);
}

// round 17
// speedup vs baseline: 1.0660x; 1.0660x over previous
#include <cuda_runtime.h>
#include <cstdint>
#include <cstddef>

// Problem constants
#define BB 32
#define TT 256
#define DD 512
#define HH 1024
#define GN 4096          // 4*H gate columns
#define MM (BB*TT)       // 8192 rows

#define NBLK 128         // persistent blocks (1/SM, all co-resident)
#define UPB 8            // hidden units per block (x4 gates = 32 cols)
#define PTH 256          // threads in persistent kernel (8 warps, 2/SMSP)

// ---------------- scratch (static device allocations; no cudaMalloc) -------
__device__ float g_zx[(size_t)MM * GN];      // input-projection Z (128 MB)
__device__ float g_h1[(size_t)MM * HH];      // layer-1 hidden history (32 MB)
__device__ float g_hT[2][HH * BB];           // transposed h double buffer [unit][batch]
__device__ unsigned g_bar_count;             // monotonic arrival counter

// ---------------- f32x2 packed FMA (Blackwell FFMA2) -----------------------
__device__ __forceinline__ float2 ffma2(float2 a, float2 b, float2 c) {
    unsigned long long au = *reinterpret_cast<unsigned long long*>(&a);
    unsigned long long bu = *reinterpret_cast<unsigned long long*>(&b);
    unsigned long long cu = *reinterpret_cast<unsigned long long*>(&c);
    unsigned long long du;
    asm("fma.rn.f32x2 %0, %1, %2, %3;" : "=l"(du) : "l"(au), "l"(bu), "l"(cu));
    return *reinterpret_cast<float2*>(&du);
}

// ---------------- fast activations (MUFU-based, inf-safe) -------------------
__device__ __forceinline__ float sig_fast(float x) {
    return __fdividef(1.f, 1.f + __expf(-x));
}
__device__ __forceinline__ float tanh_fast(float x) {
    return __fdividef(2.f, 1.f + __expf(-2.f * x)) - 1.f;
}

// ---------------- cp.async helpers ------------------------------------------
__device__ __forceinline__ void cp_async16(uint32_t dst_smem, const void* src) {
    asm volatile("cp.async.cg.shared.global [%0], [%1], 16;" :: "r"(dst_smem), "l"(src));
}
__device__ __forceinline__ void cp_commit() {
    asm volatile("cp.async.commit_group;" ::: "memory");
}
template <int N>
__device__ __forceinline__ void cp_wait() {
    asm volatile("cp.async.wait_group %0;" :: "n"(N) : "memory");
}

// ---------------- big time-parallel GEMM: C[M,N] = A[M,K] * B[K,N] ---------
#define GM_BM 128
#define GM_BN 128
#define GM_BK 16

__global__ __launch_bounds__(256, 2) void sgemm_kernel(
    const float* __restrict__ A, const float* __restrict__ B,
    float* __restrict__ C, int M, int N, int K)
{
    __shared__ float As[GM_BK][GM_BM];
    __shared__ float Bs[GM_BK][GM_BN];

    const int tid = threadIdx.x;
    const int m0 = blockIdx.y * GM_BM;
    const int n0 = blockIdx.x * GM_BN;
    const int tx = tid & 15;
    const int ty = tid >> 4;

    float2 acc2[8][4];
#pragma unroll
    for (int i = 0; i < 8; i++)
#pragma unroll
        for (int j = 0; j < 4; j++) acc2[i][j] = make_float2(0.f, 0.f);

    for (int k0 = 0; k0 < K; k0 += GM_BK) {
#pragma unroll
        for (int l = 0; l < 2; ++l) {
            int i = tid + l * 256;
            int row = i >> 2;
            int kq = (i & 3) << 2;
            float4 v = *(const float4*)(A + (size_t)(m0 + row) * K + k0 + kq);
            As[kq + 0][row] = v.x;
            As[kq + 1][row] = v.y;
            As[kq + 2][row] = v.z;
            As[kq + 3][row] = v.w;
        }
#pragma unroll
        for (int l = 0; l < 2; ++l) {
            int i = tid + l * 256;
            int kr = i >> 5;
            int nq = (i & 31) << 2;
            *(float4*)(&Bs[kr][nq]) = *(const float4*)(B + (size_t)(k0 + kr) * N + n0 + nq);
        }
        __syncthreads();

#pragma unroll
        for (int k = 0; k < GM_BK; ++k) {
            float a[8];
            *(float4*)&a[0] = *(const float4*)&As[k][ty * 4];
            *(float4*)&a[4] = *(const float4*)&As[k][64 + ty * 4];
            float4 bv0 = *(const float4*)&Bs[k][tx * 4];
            float4 bv1 = *(const float4*)&Bs[k][64 + tx * 4];
            float2 b2[4];
            b2[0] = make_float2(bv0.x, bv0.y);
            b2[1] = make_float2(bv0.z, bv0.w);
            b2[2] = make_float2(bv1.x, bv1.y);
            b2[3] = make_float2(bv1.z, bv1.w);
#pragma unroll
            for (int i = 0; i < 8; i++) {
                float2 ad = make_float2(a[i], a[i]);
#pragma unroll
                for (int jp = 0; jp < 4; jp++)
                    acc2[i][jp] = ffma2(ad, b2[jp], acc2[i][jp]);
            }
        }
        __syncthreads();
    }

#pragma unroll
    for (int i = 0; i < 8; i++) {
        int row = m0 + ((i < 4) ? (ty * 4 + i) : (64 + ty * 4 + (i - 4)));
        float* cp = C + (size_t)row * N + n0;
        float4 v0 = make_float4(acc2[i][0].x, acc2[i][0].y, acc2[i][1].x, acc2[i][1].y);
        float4 v1 = make_float4(acc2[i][2].x, acc2[i][2].y, acc2[i][3].x, acc2[i][3].y);
        *(float4*)(cp + tx * 4) = v0;
        *(float4*)(cp + 64 + tx * 4) = v1;
    }
}

// ---------------- reset: barrier counter + h state --------------------------
__global__ void reset_kernel() {
    int i = blockIdx.x * blockDim.x + threadIdx.x;
    if (i == 0) g_bar_count = 0u;
    if (i < 2 * HH * BB) ((float*)g_hT)[i] = 0.f;
}

// ---------------- persistent LSTM layer kernel -----------------------------
// 128 blocks x 256 threads (R13 best config). Block bx owns units
// [bx*8,bx*8+8) x 4 gates (32 cols). Thread (cq,bq,kq): cols {4cq..4cq+3} x
// batches {4bq..4bq+3}, K quarter kq. Per k: 1 LDS.128 w + 1 LDS.128 h
// (broadcast) -> 8 FFMA2. h streamed in 8 double-buffered cp.async chunks.
// Grid barrier: MONOTONIC counter. Arrivals are returnless red.release.add
// (no RMW round-trip, ~0.854 cyc/op at the LTS vs ~27 for atom chains); the
// condition count >= NBLK*(t+1) IS the release -- no releaser, no phase word.
__global__ __launch_bounds__(PTH, 1) void lstm_persistent(
    const float* __restrict__ Wh,       // [HH][GN] recurrent weights
    const float* __restrict__ zx,       // [MM][GN], row = b*TT + t
    const float* __restrict__ bias,     // [GN]
    float* __restrict__ hist)           // [MM][HH] h history out
{
    extern __shared__ float smem[];
    float* w_s = smem;                           // [k*32 + col], 32768 floats
    float* h_s = smem + 32768;                   // 2 x 4096 floats
    float* z_s = smem + 32768 + 2 * 4096;        // 4 x (32*36)

    const int tid = threadIdx.x;
    const int u0 = blockIdx.x * UPB;
    const int cq = tid & 7;              // col quad: cols {4cq..4cq+3}
    const int bq = (tid >> 3) & 7;       // batch quad
    const int kq = tid >> 6;             // K quarter 0..3 (uniform per warp)
    const int gu = tid & 7;              // gate-phase unit
    const int gb = tid >> 3;             // gate-phase batch 0..31

    float* hT = (float*)g_hT;

    // ---- load weight slice into smem: w_s[k*32 + cc] ----
#pragma unroll 8
    for (int l = 0; l < 128; ++l) {
        int i = tid + l * PTH;           // 0..32767
        int k = i >> 5;
        int cc = i & 31;
        int col = ((cc >> 3) << 10) + u0 + (cc & 7);
        w_s[i] = Wh[(size_t)k * GN + col];
    }

    float bi = bias[0 * HH + u0 + gu];
    float bj = bias[1 * HH + u0 + gu];
    float bf = bias[2 * HH + u0 + gu];
    float bo = bias[3 * HH + u0 + gu];

    float creg = 0.f;
    __syncthreads();

    // per-thread chunk-load geometry: 4 float4s/thread/chunk
    const int ld_row = tid >> 3;          // base row 0..31 (stride 32)
    const int ld_c4 = (tid & 7) << 2;     // 0,4,..28

    for (int t = 0; t < TT; ++t) {
        const float* hread = hT + (t & 1) * (HH * BB);
        float* hwrite = hT + ((t + 1) & 1) * (HH * BB);

        // prefetch this step's zx for the gate phase
        const float* zxr = zx + (size_t)(gb * TT + t) * GN + u0 + gu;
        float zxi = __ldg(zxr);
        float zxj = __ldg(zxr + HH);
        float zxf = __ldg(zxr + 2 * HH);
        float zxo = __ldg(zxr + 3 * HH);

        // preload chunk 0 into buffer 0
        {
            uint32_t dst = (uint32_t)__cvta_generic_to_shared(h_s);
#pragma unroll
            for (int l = 0; l < 4; ++l) {
                int row = ld_row + l * 32;
                cp_async16(dst + (row * 32 + ld_c4) * 4,
                           hread + row * BB + ld_c4);
            }
            cp_commit();
        }

        float2 alo[4], ahi[4];
#pragma unroll
        for (int c = 0; c < 4; ++c) {
            alo[c] = make_float2(0.f, 0.f);
            ahi[c] = make_float2(0.f, 0.f);
        }

#pragma unroll 1
        for (int ch = 0; ch < 8; ++ch) {
            if (ch < 7) {   // prefetch next chunk into other buffer
                float* hb_next = h_s + ((ch + 1) & 1) * 4096;
                uint32_t dst = (uint32_t)__cvta_generic_to_shared(hb_next);
                const float* src = hread + (ch + 1) * 128 * BB;
#pragma unroll
                for (int l = 0; l < 4; ++l) {
                    int row = ld_row + l * 32;
                    cp_async16(dst + (row * 32 + ld_c4) * 4,
                               src + row * BB + ld_c4);
                }
                cp_commit();
                cp_wait<1>();
            } else {
                cp_wait<0>();
            }
            __syncthreads();   // chunk ch visible to all warps

            const float* hb = h_s + (ch & 1) * 4096 + (kq * 32) * 32 + bq * 4;
            const float* wb = w_s + (ch * 128 + kq * 32) * 32 + cq * 4;
#pragma unroll 8
            for (int kk = 0; kk < 32; ++kk) {
                float4 wv = *(const float4*)(wb + kk * 32);
                float4 hv = *(const float4*)(hb + kk * 32);
                float2 hlo = make_float2(hv.x, hv.y);
                float2 hhi = make_float2(hv.z, hv.w);
                alo[0] = ffma2(hlo, make_float2(wv.x, wv.x), alo[0]);
                ahi[0] = ffma2(hhi, make_float2(wv.x, wv.x), ahi[0]);
                alo[1] = ffma2(hlo, make_float2(wv.y, wv.y), alo[1]);
                ahi[1] = ffma2(hhi, make_float2(wv.y, wv.y), ahi[1]);
                alo[2] = ffma2(hlo, make_float2(wv.z, wv.z), alo[2]);
                ahi[2] = ffma2(hhi, make_float2(wv.z, wv.z), ahi[2]);
                alo[3] = ffma2(hlo, make_float2(wv.w, wv.w), alo[3]);
                ahi[3] = ffma2(hhi, make_float2(wv.w, wv.w), ahi[3]);
            }
            __syncthreads();   // free buffer (ch&1) for chunk ch+2 prefetch
        }

        // stage K-quarter partials to smem
        float* zh = z_s + kq * (32 * 36);
#pragma unroll
        for (int c = 0; c < 4; ++c) {
            *(float4*)(zh + (cq * 4 + c) * 36 + bq * 4) =
                make_float4(alo[c].x, alo[c].y, ahi[c].x, ahi[c].y);
        }
        __syncthreads();

        // ---- gate phase: thread = (unit gu, batch gb), combine 4 quarters --
        {
            float zi = zxi + bi, zj = zxj + bj, zf = zxf + bf, zo = zxo + bo;
#pragma unroll
            for (int q = 0; q < 4; ++q) {
                const float* zq = z_s + q * (32 * 36);
                zi += zq[(0 * 8 + gu) * 36 + gb];
                zj += zq[(1 * 8 + gu) * 36 + gb];
                zf += zq[(2 * 8 + gu) * 36 + gb];
                zo += zq[(3 * 8 + gu) * 36 + gb];
            }

            float ig = sig_fast(zi);
            float fg = sig_fast(zf + 1.0f);    // forget bias 1.0
            float jt = tanh_fast(zj);
            float cn = fg * creg + ig * jt;
            float og = sig_fast(zo);
            float hn = og * tanh_fast(cn);
            creg = cn;

            hwrite[(u0 + gu) * BB + gb] = hn;
            hist[(size_t)(gb * TT + t) * HH + u0 + gu] = hn;
        }

        // ---- monotonic-counter grid barrier, returnless arrivals ----
        if (t < TT - 1) {
            __syncthreads();   // block's h writes issued (also z_s guard)
            unsigned target = (unsigned)(t + 1) * NBLK;
            if (tid == 0) {
                // release-arrive: orders this block's h stores before the add
                asm volatile("red.release.gpu.global.add.u32 [%0], %1;"
                             :: "l"(&g_bar_count), "r"(1u) : "memory");
                unsigned v;
                do {
                    asm volatile("ld.acquire.gpu.global.u32 %0, [%1];"
                                 : "=r"(v) : "l"(&g_bar_count) : "memory");
                    if (v >= target) break;
                    __nanosleep(32);
                } while (true);
            }
            __syncthreads();
        } else {
            __syncthreads();
        }
    }
}

// ---------------- host orchestration ---------------------------------------
extern "C" void kernel_launch(void* const* d_in, const int* in_sizes, int n_in,
                              void* d_out, int out_size)
{
    const float *x = nullptr, *W1 = nullptr, *b1 = nullptr, *W2 = nullptr, *b2 = nullptr;
    for (int i = 0; i < n_in; i++) {
        int s = in_sizes[i];
        const float* p = (const float*)d_in[i];
        if (s == BB * TT * DD) x = p;
        else if (s == (DD + HH) * GN) W1 = p;
        else if (s == (HH + HH) * GN) W2 = p;
        else if (s == GN) { if (!b1) b1 = p; else b2 = p; }
    }
    float* out = (float*)d_out;

    float *zx, *h1;
    { void* p; cudaGetSymbolAddress(&p, g_zx); zx = (float*)p; }
    { void* p; cudaGetSymbolAddress(&p, g_h1); h1 = (float*)p; }

    const int SMEM_BYTES = (32768 + 2 * 4096 + 4 * 32 * 36) * 4;   // ~182 KB
    cudaFuncSetAttribute(lstm_persistent,
                         cudaFuncAttributeMaxDynamicSharedMemorySize, SMEM_BYTES);

    dim3 gemm_grid(GN / GM_BN, MM / GM_BM);   // (32, 64)

    // ---- Layer 1 ----
    sgemm_kernel<<<gemm_grid, 256>>>(x, W1, zx, MM, GN, DD);
    reset_kernel<<<(2 * HH * BB + 255) / 256, 256>>>();
    // extra (idempotent) reset keeps lstm_persistent as ncu's captured launch
    reset_kernel<<<(2 * HH * BB + 255) / 256, 256>>>();
    lstm_persistent<<<NBLK, PTH, SMEM_BYTES>>>(W1 + (size_t)DD * GN, zx, b1, h1);

    // ---- Layer 2 ----
    sgemm_kernel<<<gemm_grid, 256>>>(h1, W2, zx, MM, GN, HH);
    reset_kernel<<<(2 * HH * BB + 255) / 256, 256>>>();
    lstm_persistent<<<NBLK, PTH, SMEM_BYTES>>>(W2 + (size_t)HH * GN, zx, b2, out);
}